// round 11
// baseline (speedup 1.0000x reference)
#include <cuda_runtime.h>
#include <cuda_fp16.h>
#include <cstdint>

#define NN   50000
#define EE   800000
#define ETOT 850000   // E + N self loops
#define F1   128      // HEADS*HID
#define H    4
#define FOUT 32
#define NB   196      // ceil(NN/256)

// ---------------- scratch (device globals; no allocations allowed) ----------
__device__ __align__(16) __half g_h1h[NN * F1];   // layer1 features (fp16)
__device__ __align__(16) float  g_out1[NN * F1];  // layer1 aggregate (fp32)
__device__ __align__(16) float  g_als1[NN * H];
__device__ __align__(16) float  g_ald1[NN * H];
__device__ __align__(16) __half g_h2h[NN * FOUT]; // layer2 features (fp16)
__device__ __align__(16) float  g_als2[NN];
__device__ __align__(16) float  g_ald2[NN];
__device__ int g_src[ETOT];
__device__ int g_dst[ETOT];
__device__ int g_cnt[NN];
__device__ int g_cursor[NN];
__device__ int g_rowptr[NN + 1];
__device__ int g_ssrc[ETOT];
__device__ int g_is64;

// ---------------- helpers ---------------------------------------------------
__device__ __forceinline__ float lrelu(float v) { return v > 0.f ? v : 0.2f * v; }
__device__ __forceinline__ uint32_t f2tf(float f) {
    uint32_t u; asm("cvt.rna.tf32.f32 %0, %1;" : "=r"(u) : "f"(f)); return u;
}
__device__ __forceinline__ float eluf(float v) {
    return v > 0.f ? v : __expf(v) - 1.f;
}

// ---------------- init: dtype detect (block 0) + zero counters ---------------
__global__ void k_init(const int* __restrict__ ei32) {
    int b = blockIdx.x, tid = threadIdx.x;
    if (b == 0) {
        __shared__ int any_nonzero;
        if (tid == 0) any_nonzero = 0;
        __syncthreads();
        if (ei32[2 * (tid * 1237) + 1] != 0) atomicOr(&any_nonzero, 1);
        __syncthreads();
        if (tid == 0) g_is64 = any_nonzero ? 0 : 1;
    }
    int i = b * 256 + tid;
    if (i < NN) g_cnt[i] = 0;
}

// ---------------- decode + histogram fused ------------------------------------
__global__ void k_decode(const void* __restrict__ ei) {
    int i = blockIdx.x * blockDim.x + threadIdx.x;
    if (i >= ETOT) return;
    int s, d;
    if (i >= EE) {
        s = d = i - EE;
    } else if (g_is64) {
        const long long* p = (const long long*)ei;
        s = (int)p[i]; d = (int)p[EE + i];
    } else {
        const int* q = (const int*)ei;
        s = q[i]; d = q[EE + i];
    }
    if ((unsigned)s >= NN) s = 0;
    if ((unsigned)d >= NN) d = 0;
    g_src[i] = s;
    g_dst[i] = d;
    atomicAdd(&g_cnt[d], 1);
}

// ---------------- single-block exclusive scan (1024 threads) ------------------
__global__ void k_scan() {
    int tid = threadIdx.x;
    const int CH = (NN + 1023) / 1024;   // 49
    int lo = tid * CH, hi = lo + CH;
    if (hi > NN) hi = NN;
    if (lo > NN) lo = NN;
    int sum = 0;
    for (int i = lo; i < hi; i++) sum += g_cnt[i];
    int lane = tid & 31, wid = tid >> 5;
    int v = sum;
#pragma unroll
    for (int off = 1; off < 32; off <<= 1) {
        int n = __shfl_up_sync(0xffffffffu, v, off);
        if (lane >= off) v += n;
    }
    __shared__ int ws[32];
    if (lane == 31) ws[wid] = v;
    __syncthreads();
    if (wid == 0) {
        int s = ws[lane];
#pragma unroll
        for (int off = 1; off < 32; off <<= 1) {
            int n = __shfl_up_sync(0xffffffffu, s, off);
            if (lane >= off) s += n;
        }
        ws[lane] = s;
    }
    __syncthreads();
    int run = v - sum + (wid ? ws[wid - 1] : 0);   // exclusive prefix
    for (int i = lo; i < hi; i++) {
        g_rowptr[i] = run;
        g_cursor[i] = run;
        run += g_cnt[i];
    }
    if (tid == 0) g_rowptr[NN] = ETOT;
}

__global__ void k_scatter() {
    int i = blockIdx.x * blockDim.x + threadIdx.x;
    if (i >= ETOT) return;
    int d = g_dst[i];
    int pos = atomicAdd(&g_cursor[d], 1);
    g_ssrc[pos] = g_src[i];
}

// ---------------- GEMM1 (tf32) + attention-scalar epilogue --------------------
// h1 = x @ W1 (fp16 out); als1/ald1 computed from fp32 accumulators.
__global__ __launch_bounds__(256) void k_gemm1(const float* __restrict__ x,
                                               const float* __restrict__ W,
                                               const float* __restrict__ a_src,
                                               const float* __restrict__ a_dst) {
    __shared__ uint32_t Ws[16 * 136];
    __shared__ float As[128], Ad[128];
    int tid  = threadIdx.x;
    int w    = tid >> 5;
    int lane = tid & 31;
    int g    = lane >> 2;
    int t    = lane & 3;
    int bm   = blockIdx.x * 128;

    if (tid < 128) { As[tid] = a_src[tid]; Ad[tid] = a_dst[tid]; }

    int row0 = bm + w * 16 + g;
    int row1 = row0 + 8;
    bool ok0 = row0 < NN, ok1 = row1 < NN;
    const float* xr0 = x + (size_t)(ok0 ? row0 : 0) * 128;
    const float* xr1 = x + (size_t)(ok1 ? row1 : 0) * 128;

    float acc[16][4];
#pragma unroll
    for (int n = 0; n < 16; n++)
#pragma unroll
        for (int j = 0; j < 4; j++) acc[n][j] = 0.f;

    for (int chunk = 0; chunk < 8; chunk++) {
        const float4* Wg = (const float4*)(W + chunk * 16 * 128);
#pragma unroll
        for (int r = 0; r < 2; r++) {
            int idx = tid + r * 256;
            int row = idx >> 5, cv = idx & 31;
            float4 wv = Wg[row * 32 + cv];
            uint4 tv = make_uint4(f2tf(wv.x), f2tf(wv.y), f2tf(wv.z), f2tf(wv.w));
            *(uint4*)(Ws + row * 136 + cv * 4) = tv;
        }
        __syncthreads();
#pragma unroll
        for (int ks = 0; ks < 2; ks++) {
            int k0 = chunk * 16 + ks * 8;
            int kk = ks * 8;
            uint32_t a0 = ok0 ? f2tf(xr0[k0 + t])     : 0u;
            uint32_t a2 = ok0 ? f2tf(xr0[k0 + t + 4]) : 0u;
            uint32_t a1 = ok1 ? f2tf(xr1[k0 + t])     : 0u;
            uint32_t a3 = ok1 ? f2tf(xr1[k0 + t + 4]) : 0u;
#pragma unroll
            for (int n = 0; n < 16; n++) {
                uint32_t b0 = Ws[(kk + t) * 136 + n * 8 + g];
                uint32_t b1 = Ws[(kk + t + 4) * 136 + n * 8 + g];
                asm volatile(
                    "mma.sync.aligned.m16n8k8.row.col.f32.tf32.tf32.f32 "
                    "{%0,%1,%2,%3}, {%4,%5,%6,%7}, {%8,%9}, {%0,%1,%2,%3};"
                    : "+f"(acc[n][0]), "+f"(acc[n][1]), "+f"(acc[n][2]), "+f"(acc[n][3])
                    : "r"(a0), "r"(a1), "r"(a2), "r"(a3), "r"(b0), "r"(b1));
            }
        }
        __syncthreads();
    }

    // ---- feature store (fp16) ----
#pragma unroll
    for (int n = 0; n < 16; n++) {
        if (ok0) *(__half2*)(g_h1h + (size_t)row0 * 128 + n * 8 + 2 * t) =
            __floats2half2_rn(acc[n][0], acc[n][1]);
        if (ok1) *(__half2*)(g_h1h + (size_t)row1 * 128 + n * 8 + 2 * t) =
            __floats2half2_rn(acc[n][2], acc[n][3]);
    }

    // ---- attention scalar epilogue: per-head dot products, reduce over t ----
    float s0[H] = {0,0,0,0}, d0[H] = {0,0,0,0};
    float s1[H] = {0,0,0,0}, d1[H] = {0,0,0,0};
#pragma unroll
    for (int n = 0; n < 16; n++) {
        int h = n >> 2;
        float A0 = As[n * 8 + 2 * t], A1 = As[n * 8 + 2 * t + 1];
        float D0 = Ad[n * 8 + 2 * t], D1 = Ad[n * 8 + 2 * t + 1];
        s0[h] += acc[n][0] * A0 + acc[n][1] * A1;
        d0[h] += acc[n][0] * D0 + acc[n][1] * D1;
        s1[h] += acc[n][2] * A0 + acc[n][3] * A1;
        d1[h] += acc[n][2] * D0 + acc[n][3] * D1;
    }
#pragma unroll
    for (int h = 0; h < H; h++) {
        s0[h] += __shfl_xor_sync(0xffffffffu, s0[h], 1);
        s0[h] += __shfl_xor_sync(0xffffffffu, s0[h], 2);
        d0[h] += __shfl_xor_sync(0xffffffffu, d0[h], 1);
        d0[h] += __shfl_xor_sync(0xffffffffu, d0[h], 2);
        s1[h] += __shfl_xor_sync(0xffffffffu, s1[h], 1);
        s1[h] += __shfl_xor_sync(0xffffffffu, s1[h], 2);
        d1[h] += __shfl_xor_sync(0xffffffffu, d1[h], 1);
        d1[h] += __shfl_xor_sync(0xffffffffu, d1[h], 2);
    }
    if (t == 0) {
        if (ok0) {
            *(float4*)(g_als1 + row0 * 4) = make_float4(s0[0], s0[1], s0[2], s0[3]);
            *(float4*)(g_ald1 + row0 * 4) = make_float4(d0[0], d0[1], d0[2], d0[3]);
        }
        if (ok1) {
            *(float4*)(g_als1 + row1 * 4) = make_float4(s1[0], s1[1], s1[2], s1[3]);
            *(float4*)(g_ald1 + row1 * 4) = make_float4(d1[0], d1[1], d1[2], d1[3]);
        }
    }
}

// ---------------- layer1 fused softmax+aggregate: warp per node, unroll 4 ----
__global__ void k_fagg1(const float* __restrict__ b1) {
    int w = (blockIdx.x * blockDim.x + threadIdx.x) >> 5;
    int lane = threadIdx.x & 31;
    if (w >= NN) return;
    int beg = g_rowptr[w], end = g_rowptr[w + 1];
    int head = lane >> 3;
    float ald = g_ald1[w * 4 + head];
    float4 acc = make_float4(0.f, 0.f, 0.f, 0.f);
    float denom = 0.f;
    int e = beg;
    for (; e + 4 <= end; e += 4) {
        int s0 = g_ssrc[e],     s1 = g_ssrc[e + 1];
        int s2 = g_ssrc[e + 2], s3 = g_ssrc[e + 3];
        float p0 = __expf(lrelu(g_als1[s0 * 4 + head] + ald));
        float p1 = __expf(lrelu(g_als1[s1 * 4 + head] + ald));
        float p2 = __expf(lrelu(g_als1[s2 * 4 + head] + ald));
        float p3 = __expf(lrelu(g_als1[s3 * 4 + head] + ald));
        const __half2* h0 = (const __half2*)(g_h1h + (size_t)s0 * 128) + lane * 2;
        const __half2* h1 = (const __half2*)(g_h1h + (size_t)s1 * 128) + lane * 2;
        const __half2* h2 = (const __half2*)(g_h1h + (size_t)s2 * 128) + lane * 2;
        const __half2* h3 = (const __half2*)(g_h1h + (size_t)s3 * 128) + lane * 2;
        float2 a0 = __half22float2(h0[0]), b0v = __half22float2(h0[1]);
        float2 a1 = __half22float2(h1[0]), b1v = __half22float2(h1[1]);
        float2 a2 = __half22float2(h2[0]), b2v = __half22float2(h2[1]);
        float2 a3 = __half22float2(h3[0]), b3v = __half22float2(h3[1]);
        denom += (p0 + p1) + (p2 + p3);
        acc.x += p0 * a0.x + p1 * a1.x + p2 * a2.x + p3 * a3.x;
        acc.y += p0 * a0.y + p1 * a1.y + p2 * a2.y + p3 * a3.y;
        acc.z += p0 * b0v.x + p1 * b1v.x + p2 * b2v.x + p3 * b3v.x;
        acc.w += p0 * b0v.y + p1 * b1v.y + p2 * b2v.y + p3 * b3v.y;
    }
    for (; e < end; e++) {
        int s0 = g_ssrc[e];
        float p0 = __expf(lrelu(g_als1[s0 * 4 + head] + ald));
        const __half2* h0 = (const __half2*)(g_h1h + (size_t)s0 * 128) + lane * 2;
        float2 a0 = __half22float2(h0[0]), b0v = __half22float2(h0[1]);
        denom += p0;
        acc.x += p0 * a0.x; acc.y += p0 * a0.y;
        acc.z += p0 * b0v.x; acc.w += p0 * b0v.y;
    }
    float inv = 1.f / fmaxf(denom, 1e-16f);
    float4 bias = *(const float4*)(b1 + lane * 4);
    acc.x = acc.x * inv + bias.x;
    acc.y = acc.y * inv + bias.y;
    acc.z = acc.z * inv + bias.z;
    acc.w = acc.w * inv + bias.w;
    *(float4*)(g_out1 + (size_t)w * 128 + lane * 4) = acc;
}

// ---------------- GEMM2 (tf32, ELU fused) + attention-scalar epilogue --------
__global__ __launch_bounds__(256) void k_gemm2(const float* __restrict__ W,
                                               const float* __restrict__ a_src,
                                               const float* __restrict__ a_dst) {
    __shared__ uint32_t Ws[128 * 40];
    __shared__ float As[32], Ad[32];
    int tid  = threadIdx.x;
    int w    = tid >> 5;
    int lane = tid & 31;
    int g    = lane >> 2;
    int t    = lane & 3;
    int bm   = blockIdx.x * 128;

    if (tid < 32) { As[tid] = a_src[tid]; Ad[tid] = a_dst[tid]; }

    const float4* Wg = (const float4*)W;
#pragma unroll
    for (int r = 0; r < 4; r++) {
        int idx = tid + r * 256;
        int row = idx >> 3, cv = idx & 7;
        float4 wv = Wg[row * 8 + cv];
        uint4 tv = make_uint4(f2tf(wv.x), f2tf(wv.y), f2tf(wv.z), f2tf(wv.w));
        *(uint4*)(Ws + row * 40 + cv * 4) = tv;
    }
    __syncthreads();

    int row0 = bm + w * 16 + g;
    int row1 = row0 + 8;
    bool ok0 = row0 < NN, ok1 = row1 < NN;
    const float* xr0 = g_out1 + (size_t)(ok0 ? row0 : 0) * 128;
    const float* xr1 = g_out1 + (size_t)(ok1 ? row1 : 0) * 128;

    float acc[4][4];
#pragma unroll
    for (int n = 0; n < 4; n++)
#pragma unroll
        for (int j = 0; j < 4; j++) acc[n][j] = 0.f;

#pragma unroll
    for (int ks = 0; ks < 16; ks++) {
        int k0 = ks * 8;
        uint32_t a0 = ok0 ? f2tf(eluf(xr0[k0 + t]))     : 0u;
        uint32_t a2 = ok0 ? f2tf(eluf(xr0[k0 + t + 4])) : 0u;
        uint32_t a1 = ok1 ? f2tf(eluf(xr1[k0 + t]))     : 0u;
        uint32_t a3 = ok1 ? f2tf(eluf(xr1[k0 + t + 4])) : 0u;
#pragma unroll
        for (int n = 0; n < 4; n++) {
            uint32_t b0 = Ws[(k0 + t) * 40 + n * 8 + g];
            uint32_t b1 = Ws[(k0 + t + 4) * 40 + n * 8 + g];
            asm volatile(
                "mma.sync.aligned.m16n8k8.row.col.f32.tf32.tf32.f32 "
                "{%0,%1,%2,%3}, {%4,%5,%6,%7}, {%8,%9}, {%0,%1,%2,%3};"
                : "+f"(acc[n][0]), "+f"(acc[n][1]), "+f"(acc[n][2]), "+f"(acc[n][3])
                : "r"(a0), "r"(a1), "r"(a2), "r"(a3), "r"(b0), "r"(b1));
        }
    }
#pragma unroll
    for (int n = 0; n < 4; n++) {
        if (ok0) *(__half2*)(g_h2h + (size_t)row0 * 32 + n * 8 + 2 * t) =
            __floats2half2_rn(acc[n][0], acc[n][1]);
        if (ok1) *(__half2*)(g_h2h + (size_t)row1 * 32 + n * 8 + 2 * t) =
            __floats2half2_rn(acc[n][2], acc[n][3]);
    }

    // ---- attention scalar epilogue ----
    float s0 = 0.f, d0 = 0.f, s1v = 0.f, d1v = 0.f;
#pragma unroll
    for (int n = 0; n < 4; n++) {
        float A0 = As[n * 8 + 2 * t], A1 = As[n * 8 + 2 * t + 1];
        float D0 = Ad[n * 8 + 2 * t], D1 = Ad[n * 8 + 2 * t + 1];
        s0  += acc[n][0] * A0 + acc[n][1] * A1;
        d0  += acc[n][0] * D0 + acc[n][1] * D1;
        s1v += acc[n][2] * A0 + acc[n][3] * A1;
        d1v += acc[n][2] * D0 + acc[n][3] * D1;
    }
    s0  += __shfl_xor_sync(0xffffffffu, s0, 1);
    s0  += __shfl_xor_sync(0xffffffffu, s0, 2);
    d0  += __shfl_xor_sync(0xffffffffu, d0, 1);
    d0  += __shfl_xor_sync(0xffffffffu, d0, 2);
    s1v += __shfl_xor_sync(0xffffffffu, s1v, 1);
    s1v += __shfl_xor_sync(0xffffffffu, s1v, 2);
    d1v += __shfl_xor_sync(0xffffffffu, d1v, 1);
    d1v += __shfl_xor_sync(0xffffffffu, d1v, 2);
    if (t == 0) {
        if (ok0) { g_als2[row0] = s0;  g_ald2[row0] = d0; }
        if (ok1) { g_als2[row1] = s1v; g_ald2[row1] = d1v; }
    }
}

// ---------------- layer2 fused softmax+aggregate: warp per node, unroll 4 ----
__global__ void k_fagg2(const float* __restrict__ b2, float* __restrict__ out) {
    int w = (blockIdx.x * blockDim.x + threadIdx.x) >> 5;
    int lane = threadIdx.x & 31;
    if (w >= NN) return;
    int beg = g_rowptr[w], end = g_rowptr[w + 1];
    float ald = g_ald2[w];
    float acc = 0.f, denom = 0.f;
    int e = beg;
    for (; e + 4 <= end; e += 4) {
        int s0 = g_ssrc[e],     s1 = g_ssrc[e + 1];
        int s2 = g_ssrc[e + 2], s3 = g_ssrc[e + 3];
        float p0 = __expf(lrelu(g_als2[s0] + ald));
        float p1 = __expf(lrelu(g_als2[s1] + ald));
        float p2 = __expf(lrelu(g_als2[s2] + ald));
        float p3 = __expf(lrelu(g_als2[s3] + ald));
        float v0 = __half2float(g_h2h[(size_t)s0 * 32 + lane]);
        float v1 = __half2float(g_h2h[(size_t)s1 * 32 + lane]);
        float v2 = __half2float(g_h2h[(size_t)s2 * 32 + lane]);
        float v3 = __half2float(g_h2h[(size_t)s3 * 32 + lane]);
        denom += (p0 + p1) + (p2 + p3);
        acc += p0 * v0 + p1 * v1 + p2 * v2 + p3 * v3;
    }
    for (; e < end; e++) {
        int s0 = g_ssrc[e];
        float p0 = __expf(lrelu(g_als2[s0] + ald));
        denom += p0;
        acc += p0 * __half2float(g_h2h[(size_t)s0 * 32 + lane]);
    }
    out[(size_t)w * 32 + lane] = acc / fmaxf(denom, 1e-16f) + b2[lane];
}

// ---------------- launcher ---------------------------------------------------
extern "C" void kernel_launch(void* const* d_in, const int* in_sizes, int n_in,
                              void* d_out, int out_size) {
    const float* x      = (const float*)d_in[0];
    const float* W1     = (const float*)d_in[1];
    const float* a_src1 = (const float*)d_in[2];
    const float* a_dst1 = (const float*)d_in[3];
    const float* b1     = (const float*)d_in[4];
    const float* W2     = (const float*)d_in[5];
    const float* a_src2 = (const float*)d_in[6];
    const float* a_dst2 = (const float*)d_in[7];
    const float* b2     = (const float*)d_in[8];
    const void*  ei     = (const void*)d_in[9];
    float* out = (float*)d_out;

    k_init   <<<NB, 256>>>((const int*)ei);
    k_decode <<<(ETOT + 255) / 256, 256>>>(ei);
    k_scan   <<<1, 1024>>>();
    k_scatter<<<(ETOT + 255) / 256, 256>>>();
    k_gemm1  <<<(NN + 127) / 128, 256>>>(x, W1, a_src1, a_dst1);
    k_fagg1  <<<(NN * 32 + 255) / 256, 256>>>(b1);
    k_gemm2  <<<(NN + 127) / 128, 256>>>(W2, a_src2, a_dst2);
    k_fagg2  <<<(NN * 32 + 255) / 256, 256>>>(b2, out);
}

// round 13
// speedup vs baseline: 1.3949x; 1.3949x over previous
#include <cuda_runtime.h>
#include <cuda_fp16.h>
#include <cstdint>

#define NN   50000
#define EE   800000
#define ETOT 850000   // E + N self loops
#define F1   128      // HEADS*HID
#define H    4
#define FOUT 32
#define NB   196      // ceil(NN/256)

// ---------------- scratch (device globals; no allocations allowed) ----------
__device__ __align__(16) __half g_h1h[NN * F1];   // layer1 features (fp16)
__device__ __align__(16) float  g_out1[NN * F1];  // layer1 aggregate (fp32)
__device__ __align__(16) float  g_als1[NN * H];
__device__ __align__(16) float  g_ald1[NN * H];
__device__ __align__(16) __half g_h2h[NN * FOUT]; // layer2 features (fp16)
__device__ __align__(16) float  g_als2[NN];
__device__ __align__(16) float  g_ald2[NN];
__device__ int g_src[ETOT];
__device__ int g_dst[ETOT];
__device__ int g_cnt[NN];
__device__ int g_cursor[NN];
__device__ int g_rowptr[NN + 1];
__device__ int g_ssrc[ETOT];
__device__ int g_bsum[NB];
__device__ int g_boff[NB];
__device__ int g_is64;

// ---------------- helpers ---------------------------------------------------
__device__ __forceinline__ float lrelu(float v) { return v > 0.f ? v : 0.2f * v; }
__device__ __forceinline__ uint32_t f2tf(float f) {
    uint32_t u; asm("cvt.rna.tf32.f32 %0, %1;" : "=r"(u) : "f"(f)); return u;
}
__device__ __forceinline__ float eluf(float v) {
    return v > 0.f ? v : __expf(v) - 1.f;
}

// ---------------- init: dtype detect (block 0) + zero counters ---------------
__global__ void k_init(const int* __restrict__ ei32) {
    int b = blockIdx.x, tid = threadIdx.x;
    if (b == 0) {
        __shared__ int any_nonzero;
        if (tid == 0) any_nonzero = 0;
        __syncthreads();
        if (ei32[2 * (tid * 1237) + 1] != 0) atomicOr(&any_nonzero, 1);
        __syncthreads();
        if (tid == 0) g_is64 = any_nonzero ? 0 : 1;
    }
    int i = b * 256 + tid;
    if (i < NN) g_cnt[i] = 0;
}

// ---------------- decode + histogram fused ------------------------------------
__global__ void k_decode(const void* __restrict__ ei) {
    int i = blockIdx.x * blockDim.x + threadIdx.x;
    if (i >= ETOT) return;
    int s, d;
    if (i >= EE) {
        s = d = i - EE;
    } else if (g_is64) {
        const long long* p = (const long long*)ei;
        s = (int)p[i]; d = (int)p[EE + i];
    } else {
        const int* q = (const int*)ei;
        s = q[i]; d = q[EE + i];
    }
    if ((unsigned)s >= NN) s = 0;
    if ((unsigned)d >= NN) d = 0;
    g_src[i] = s;
    g_dst[i] = d;
    atomicAdd(&g_cnt[d], 1);
}

// ---------------- parallel 3-stage exclusive scan of g_cnt (coalesced) -------
__global__ void k_scanA() {
    int b = blockIdx.x, tid = threadIdx.x;
    int i = b * 256 + tid;
    int c = (i < NN) ? g_cnt[i] : 0;
    int lane = tid & 31, wid = tid >> 5;
#pragma unroll
    for (int off = 16; off; off >>= 1) c += __shfl_down_sync(0xffffffffu, c, off);
    __shared__ int ws[8];
    if (lane == 0) ws[wid] = c;
    __syncthreads();
    if (tid == 0) {
        int s = 0;
#pragma unroll
        for (int j = 0; j < 8; j++) s += ws[j];
        g_bsum[b] = s;
    }
}

__global__ void k_scanB() {   // 1 block, 256 threads
    int tid = threadIdx.x;
    __shared__ int sh[256];
    int v = (tid < NB) ? g_bsum[tid] : 0;
    sh[tid] = v;
    __syncthreads();
    for (int off = 1; off < 256; off <<= 1) {
        int n = (tid >= off) ? sh[tid - off] : 0;
        __syncthreads();
        sh[tid] += n;
        __syncthreads();
    }
    if (tid < NB) g_boff[tid] = sh[tid] - v;   // exclusive
}

__global__ void k_scanC() {
    int b = blockIdx.x, tid = threadIdx.x;
    int i = b * 256 + tid;
    int c = (i < NN) ? g_cnt[i] : 0;
    int lane = tid & 31, wid = tid >> 5;
    int v = c;
#pragma unroll
    for (int off = 1; off < 32; off <<= 1) {
        int n = __shfl_up_sync(0xffffffffu, v, off);
        if (lane >= off) v += n;
    }
    __shared__ int ws[8];
    if (lane == 31) ws[wid] = v;
    __syncthreads();
    if (wid == 0) {
        int s = (lane < 8) ? ws[lane] : 0;
#pragma unroll
        for (int off = 1; off < 8; off <<= 1) {
            int n = __shfl_up_sync(0xffffffffu, s, off);
            if (lane >= off) s += n;
        }
        if (lane < 8) ws[lane] = s;
    }
    __syncthreads();
    int excl = v - c + (wid ? ws[wid - 1] : 0) + g_boff[b];
    if (i < NN) { g_rowptr[i] = excl; g_cursor[i] = excl; }
    if (i == 0) g_rowptr[NN] = ETOT;
}

__global__ void k_scatter() {
    int i = blockIdx.x * blockDim.x + threadIdx.x;
    if (i >= ETOT) return;
    int d = g_dst[i];
    int pos = atomicAdd(&g_cursor[d], 1);
    g_ssrc[pos] = g_src[i];
}

// ---------------- GEMM1 (tf32 tensor cores): h1 = x @ W1, fp16 out -----------
__global__ __launch_bounds__(256) void k_gemm1(const float* __restrict__ x,
                                               const float* __restrict__ W) {
    __shared__ uint32_t Ws[16 * 136];
    int tid  = threadIdx.x;
    int w    = tid >> 5;
    int lane = tid & 31;
    int g    = lane >> 2;
    int t    = lane & 3;
    int bm   = blockIdx.x * 128;

    int row0 = bm + w * 16 + g;
    int row1 = row0 + 8;
    bool ok0 = row0 < NN, ok1 = row1 < NN;
    const float* xr0 = x + (size_t)(ok0 ? row0 : 0) * 128;
    const float* xr1 = x + (size_t)(ok1 ? row1 : 0) * 128;

    float acc[16][4];
#pragma unroll
    for (int n = 0; n < 16; n++)
#pragma unroll
        for (int j = 0; j < 4; j++) acc[n][j] = 0.f;

    for (int chunk = 0; chunk < 8; chunk++) {
        const float4* Wg = (const float4*)(W + chunk * 16 * 128);
#pragma unroll
        for (int r = 0; r < 2; r++) {
            int idx = tid + r * 256;
            int row = idx >> 5, cv = idx & 31;
            float4 wv = Wg[row * 32 + cv];
            uint4 tv = make_uint4(f2tf(wv.x), f2tf(wv.y), f2tf(wv.z), f2tf(wv.w));
            *(uint4*)(Ws + row * 136 + cv * 4) = tv;
        }
        __syncthreads();
#pragma unroll
        for (int ks = 0; ks < 2; ks++) {
            int k0 = chunk * 16 + ks * 8;
            int kk = ks * 8;
            uint32_t a0 = ok0 ? f2tf(xr0[k0 + t])     : 0u;
            uint32_t a2 = ok0 ? f2tf(xr0[k0 + t + 4]) : 0u;
            uint32_t a1 = ok1 ? f2tf(xr1[k0 + t])     : 0u;
            uint32_t a3 = ok1 ? f2tf(xr1[k0 + t + 4]) : 0u;
#pragma unroll
            for (int n = 0; n < 16; n++) {
                uint32_t b0 = Ws[(kk + t) * 136 + n * 8 + g];
                uint32_t b1 = Ws[(kk + t + 4) * 136 + n * 8 + g];
                asm volatile(
                    "mma.sync.aligned.m16n8k8.row.col.f32.tf32.tf32.f32 "
                    "{%0,%1,%2,%3}, {%4,%5,%6,%7}, {%8,%9}, {%0,%1,%2,%3};"
                    : "+f"(acc[n][0]), "+f"(acc[n][1]), "+f"(acc[n][2]), "+f"(acc[n][3])
                    : "r"(a0), "r"(a1), "r"(a2), "r"(a3), "r"(b0), "r"(b1));
            }
        }
        __syncthreads();
    }
#pragma unroll
    for (int n = 0; n < 16; n++) {
        if (ok0) *(__half2*)(g_h1h + (size_t)row0 * 128 + n * 8 + 2 * t) =
            __floats2half2_rn(acc[n][0], acc[n][1]);
        if (ok1) *(__half2*)(g_h1h + (size_t)row1 * 128 + n * 8 + 2 * t) =
            __floats2half2_rn(acc[n][2], acc[n][3]);
    }
}

// ---------------- attention scalars layer1 (fp16 h1) -------------------------
__global__ void k_al1(const float* __restrict__ a_src, const float* __restrict__ a_dst) {
    int i = blockIdx.x * blockDim.x + threadIdx.x;
    if (i >= NN * H) return;
    int n = i >> 2, h = i & 3;
    const __half2* hp = (const __half2*)(g_h1h + (size_t)n * 128 + h * 32);
    float s = 0.f, d = 0.f;
#pragma unroll
    for (int j = 0; j < 16; j++) {
        float2 v = __half22float2(hp[j]);
        float as0 = a_src[h * 32 + 2 * j], as1 = a_src[h * 32 + 2 * j + 1];
        float ad0 = a_dst[h * 32 + 2 * j], ad1 = a_dst[h * 32 + 2 * j + 1];
        s += v.x * as0 + v.y * as1;
        d += v.x * ad0 + v.y * ad1;
    }
    g_als1[i] = s;
    g_ald1[i] = d;
}

// ---------------- layer1 fused softmax+aggregate: warp per node, unroll 4 ----
__global__ void k_fagg1(const float* __restrict__ b1) {
    int w = (blockIdx.x * blockDim.x + threadIdx.x) >> 5;
    int lane = threadIdx.x & 31;
    if (w >= NN) return;
    int beg = g_rowptr[w], end = g_rowptr[w + 1];
    int head = lane >> 3;
    float ald = g_ald1[w * 4 + head];
    float4 acc = make_float4(0.f, 0.f, 0.f, 0.f);
    float denom = 0.f;
    int e = beg;
    for (; e + 4 <= end; e += 4) {
        int s0 = g_ssrc[e],     s1 = g_ssrc[e + 1];
        int s2 = g_ssrc[e + 2], s3 = g_ssrc[e + 3];
        float p0 = __expf(lrelu(g_als1[s0 * 4 + head] + ald));
        float p1 = __expf(lrelu(g_als1[s1 * 4 + head] + ald));
        float p2 = __expf(lrelu(g_als1[s2 * 4 + head] + ald));
        float p3 = __expf(lrelu(g_als1[s3 * 4 + head] + ald));
        const __half2* h0 = (const __half2*)(g_h1h + (size_t)s0 * 128) + lane * 2;
        const __half2* h1 = (const __half2*)(g_h1h + (size_t)s1 * 128) + lane * 2;
        const __half2* h2 = (const __half2*)(g_h1h + (size_t)s2 * 128) + lane * 2;
        const __half2* h3 = (const __half2*)(g_h1h + (size_t)s3 * 128) + lane * 2;
        float2 a0 = __half22float2(h0[0]), b0v = __half22float2(h0[1]);
        float2 a1 = __half22float2(h1[0]), b1v = __half22float2(h1[1]);
        float2 a2 = __half22float2(h2[0]), b2v = __half22float2(h2[1]);
        float2 a3 = __half22float2(h3[0]), b3v = __half22float2(h3[1]);
        denom += (p0 + p1) + (p2 + p3);
        acc.x += p0 * a0.x + p1 * a1.x + p2 * a2.x + p3 * a3.x;
        acc.y += p0 * a0.y + p1 * a1.y + p2 * a2.y + p3 * a3.y;
        acc.z += p0 * b0v.x + p1 * b1v.x + p2 * b2v.x + p3 * b3v.x;
        acc.w += p0 * b0v.y + p1 * b1v.y + p2 * b2v.y + p3 * b3v.y;
    }
    for (; e < end; e++) {
        int s0 = g_ssrc[e];
        float p0 = __expf(lrelu(g_als1[s0 * 4 + head] + ald));
        const __half2* h0 = (const __half2*)(g_h1h + (size_t)s0 * 128) + lane * 2;
        float2 a0 = __half22float2(h0[0]), b0v = __half22float2(h0[1]);
        denom += p0;
        acc.x += p0 * a0.x; acc.y += p0 * a0.y;
        acc.z += p0 * b0v.x; acc.w += p0 * b0v.y;
    }
    float inv = 1.f / fmaxf(denom, 1e-16f);
    float4 bias = *(const float4*)(b1 + lane * 4);
    acc.x = acc.x * inv + bias.x;
    acc.y = acc.y * inv + bias.y;
    acc.z = acc.z * inv + bias.z;
    acc.w = acc.w * inv + bias.w;
    *(float4*)(g_out1 + (size_t)w * 128 + lane * 4) = acc;
}

// ---------------- GEMM2 (tf32, ELU fused): h2 = elu(out1) @ W2, fp16 out -----
__global__ __launch_bounds__(256) void k_gemm2(const float* __restrict__ W) {
    __shared__ uint32_t Ws[128 * 40];
    int tid  = threadIdx.x;
    int w    = tid >> 5;
    int lane = tid & 31;
    int g    = lane >> 2;
    int t    = lane & 3;
    int bm   = blockIdx.x * 128;

    const float4* Wg = (const float4*)W;
#pragma unroll
    for (int r = 0; r < 4; r++) {
        int idx = tid + r * 256;
        int row = idx >> 3, cv = idx & 7;
        float4 wv = Wg[row * 8 + cv];
        uint4 tv = make_uint4(f2tf(wv.x), f2tf(wv.y), f2tf(wv.z), f2tf(wv.w));
        *(uint4*)(Ws + row * 40 + cv * 4) = tv;
    }
    __syncthreads();

    int row0 = bm + w * 16 + g;
    int row1 = row0 + 8;
    bool ok0 = row0 < NN, ok1 = row1 < NN;
    const float* xr0 = g_out1 + (size_t)(ok0 ? row0 : 0) * 128;
    const float* xr1 = g_out1 + (size_t)(ok1 ? row1 : 0) * 128;

    float acc[4][4];
#pragma unroll
    for (int n = 0; n < 4; n++)
#pragma unroll
        for (int j = 0; j < 4; j++) acc[n][j] = 0.f;

#pragma unroll
    for (int ks = 0; ks < 16; ks++) {
        int k0 = ks * 8;
        uint32_t a0 = ok0 ? f2tf(eluf(xr0[k0 + t]))     : 0u;
        uint32_t a2 = ok0 ? f2tf(eluf(xr0[k0 + t + 4])) : 0u;
        uint32_t a1 = ok1 ? f2tf(eluf(xr1[k0 + t]))     : 0u;
        uint32_t a3 = ok1 ? f2tf(eluf(xr1[k0 + t + 4])) : 0u;
#pragma unroll
        for (int n = 0; n < 4; n++) {
            uint32_t b0 = Ws[(k0 + t) * 40 + n * 8 + g];
            uint32_t b1 = Ws[(k0 + t + 4) * 40 + n * 8 + g];
            asm volatile(
                "mma.sync.aligned.m16n8k8.row.col.f32.tf32.tf32.f32 "
                "{%0,%1,%2,%3}, {%4,%5,%6,%7}, {%8,%9}, {%0,%1,%2,%3};"
                : "+f"(acc[n][0]), "+f"(acc[n][1]), "+f"(acc[n][2]), "+f"(acc[n][3])
                : "r"(a0), "r"(a1), "r"(a2), "r"(a3), "r"(b0), "r"(b1));
        }
    }
#pragma unroll
    for (int n = 0; n < 4; n++) {
        if (ok0) *(__half2*)(g_h2h + (size_t)row0 * 32 + n * 8 + 2 * t) =
            __floats2half2_rn(acc[n][0], acc[n][1]);
        if (ok1) *(__half2*)(g_h2h + (size_t)row1 * 32 + n * 8 + 2 * t) =
            __floats2half2_rn(acc[n][2], acc[n][3]);
    }
}

// ---------------- attention scalars layer2 (fp16 h2) -------------------------
__global__ void k_al2(const float* __restrict__ a_src, const float* __restrict__ a_dst) {
    int n = blockIdx.x * blockDim.x + threadIdx.x;
    if (n >= NN) return;
    const __half2* hp = (const __half2*)(g_h2h + (size_t)n * 32);
    float s = 0.f, d = 0.f;
#pragma unroll
    for (int j = 0; j < 16; j++) {
        float2 v = __half22float2(hp[j]);
        s += v.x * a_src[2 * j] + v.y * a_src[2 * j + 1];
        d += v.x * a_dst[2 * j] + v.y * a_dst[2 * j + 1];
    }
    g_als2[n] = s;
    g_ald2[n] = d;
}

// ---------------- layer2 fused softmax+aggregate: warp per node, unroll 4 ----
__global__ void k_fagg2(const float* __restrict__ b2, float* __restrict__ out) {
    int w = (blockIdx.x * blockDim.x + threadIdx.x) >> 5;
    int lane = threadIdx.x & 31;
    if (w >= NN) return;
    int beg = g_rowptr[w], end = g_rowptr[w + 1];
    float ald = g_ald2[w];
    float acc = 0.f, denom = 0.f;
    int e = beg;
    for (; e + 4 <= end; e += 4) {
        int s0 = g_ssrc[e],     s1 = g_ssrc[e + 1];
        int s2 = g_ssrc[e + 2], s3 = g_ssrc[e + 3];
        float p0 = __expf(lrelu(g_als2[s0] + ald));
        float p1 = __expf(lrelu(g_als2[s1] + ald));
        float p2 = __expf(lrelu(g_als2[s2] + ald));
        float p3 = __expf(lrelu(g_als2[s3] + ald));
        float v0 = __half2float(g_h2h[(size_t)s0 * 32 + lane]);
        float v1 = __half2float(g_h2h[(size_t)s1 * 32 + lane]);
        float v2 = __half2float(g_h2h[(size_t)s2 * 32 + lane]);
        float v3 = __half2float(g_h2h[(size_t)s3 * 32 + lane]);
        denom += (p0 + p1) + (p2 + p3);
        acc += p0 * v0 + p1 * v1 + p2 * v2 + p3 * v3;
    }
    for (; e < end; e++) {
        int s0 = g_ssrc[e];
        float p0 = __expf(lrelu(g_als2[s0] + ald));
        denom += p0;
        acc += p0 * __half2float(g_h2h[(size_t)s0 * 32 + lane]);
    }
    out[(size_t)w * 32 + lane] = acc / fmaxf(denom, 1e-16f) + b2[lane];
}

// ---------------- launcher ---------------------------------------------------
extern "C" void kernel_launch(void* const* d_in, const int* in_sizes, int n_in,
                              void* d_out, int out_size) {
    const float* x      = (const float*)d_in[0];
    const float* W1     = (const float*)d_in[1];
    const float* a_src1 = (const float*)d_in[2];
    const float* a_dst1 = (const float*)d_in[3];
    const float* b1     = (const float*)d_in[4];
    const float* W2     = (const float*)d_in[5];
    const float* a_src2 = (const float*)d_in[6];
    const float* a_dst2 = (const float*)d_in[7];
    const float* b2     = (const float*)d_in[8];
    const void*  ei     = (const void*)d_in[9];
    float* out = (float*)d_out;

    k_init   <<<NB, 256>>>((const int*)ei);
    k_decode <<<(ETOT + 255) / 256, 256>>>(ei);
    k_scanA  <<<NB, 256>>>();
    k_scanB  <<<1, 256>>>();
    k_scanC  <<<NB, 256>>>();
    k_scatter<<<(ETOT + 255) / 256, 256>>>();
    k_gemm1  <<<(NN + 127) / 128, 256>>>(x, W1);
    k_al1    <<<(NN * H + 255) / 256, 256>>>(a_src1, a_dst1);
    k_fagg1  <<<(NN * 32 + 255) / 256, 256>>>(b1);
    k_gemm2  <<<(NN + 127) / 128, 256>>>(W2);
    k_al2    <<<(NN + 255) / 256, 256>>>(a_src2, a_dst2);
    k_fagg2  <<<(NN * 32 + 255) / 256, 256>>>(b2, out);
}